// round 7
// baseline (speedup 1.0000x reference)
#include <cuda_runtime.h>
#include <cstdint>

// Chamfer distance via 1-D spatially pruned NN search.
// array1, array2 [B=4, N=4096, D=3] fp32.
// out = (100/32768) * sum over all 32768 per-point NN sq-dists (both dirs).
//
// min d2 over candidates = sq - 2*max(q.c - 0.5|c|^2)  (dot trick, same
// rounding style as the reference).
//
// Kernel 1 (prep): for each of 8 (batch, array) combos, bucket the 4096
// points by x into 512 linear buckets over [-6, 6] (clamped). Histogram via
// smem atomics, Hillis-Steele scan, atomic scatter. Within-bucket order is
// nondeterministic, but min over an identical candidate set is exact and
// order-independent -> deterministic result.
//
// Kernel 2 (search): queries stream in bucket order (warp-coherent). Each
// thread owns one query; candidates (the opposing array, bucket-ordered,
// with w = -0.5|c|^2) live in 64 KB dynamic smem. Walk buckets outward from
// the query's own bucket; stop when the nearer unvisited bucket edge already
// exceeds the current best distance:  min(dL^2, dR^2) >= sq - 2M.
// Clamp buckets keep the edge bound conservative for any input (worst case
// = correct brute force). ~300 of 4096 candidates evaluated per query vs
// 4096 -> removes the FFMA rt=2 ceiling R6 was pinned to.
//
// Block mapping: 8 combos x 16 blocks; warp j of block s handles query-warp
// s + 16*j (strided -> dense-center and sparse-tail warps mix per block).
// Final sum: per-block partial + atomic-counter last-block reduce (fixed
// read order -> deterministic).

#define NBK 512
#define XLO (-6.0f)
#define XW (12.0f / NBK)
#define XINVW (NBK / 12.0f)
#define NPTS 4096
#define SBLK 128            // search grid blocks
#define INFF __int_as_float(0x7f800000)

__device__ float4 g_sorted[8][NPTS];
__device__ int    g_bstart[8][NBK + 1];
__device__ float  g_partial[SBLK];
__device__ int    g_count;   // zero-init; self-resets each run

__device__ __forceinline__ int bucket_of(float x) {
    int bk = (int)((x - XLO) * XINVW);
    bk = bk < 0 ? 0 : bk;
    return bk > NBK - 1 ? NBK - 1 : bk;
}

// ---------------- kernel 1: bucket the 8 arrays by x ----------------
__global__ __launch_bounds__(512) void chamfer_prep(
    const float* __restrict__ a1, const float* __restrict__ a2)
{
    __shared__ int sh[NBK];    // histogram -> inclusive scan
    __shared__ int soff[NBK];  // scatter counters

    const int c = blockIdx.x;            // combo 0..7 = b*2 + arr
    const int b = c >> 1;
    const float* src = ((c & 1) ? a2 : a1) + (size_t)b * NPTS * 3;
    const int t = threadIdx.x;           // 512 == NBK

    sh[t] = 0;
    __syncthreads();

    float px[8], py[8], pz[8];
    int   bk[8];
#pragma unroll
    for (int k = 0; k < 8; k++) {
        const int i = t + k * 512;
        px[k] = src[i * 3 + 0];
        py[k] = src[i * 3 + 1];
        pz[k] = src[i * 3 + 2];
        bk[k] = bucket_of(px[k]);
        atomicAdd(&sh[bk[k]], 1);
    }
    __syncthreads();

    // Hillis-Steele inclusive scan over sh[0..NBK)
    for (int off = 1; off < NBK; off <<= 1) {
        const int v = (t >= off) ? sh[t - off] : 0;
        __syncthreads();
        sh[t] += v;
        __syncthreads();
    }

    const int e = (t == 0) ? 0 : sh[t - 1];   // exclusive start
    soff[t] = e;
    g_bstart[c][t] = e;
    if (t == 0) g_bstart[c][NBK] = NPTS;
    __syncthreads();

#pragma unroll
    for (int k = 0; k < 8; k++) {
        const int r = atomicAdd(&soff[bk[k]], 1);
        g_sorted[c][r] = make_float4(px[k], py[k], pz[k],
            -0.5f * (px[k] * px[k] + py[k] * py[k] + pz[k] * pz[k]));
    }
}

// ---------------- kernel 2: pruned NN search + full reduction ----------------
__global__ __launch_bounds__(256) void chamfer_search(float* __restrict__ out)
{
    extern __shared__ float4 scand[];        // 4096 * 16 B = 64 KB (dynamic)
    __shared__ int   sbst[NBK + 1];
    __shared__ float s_red[8];
    __shared__ int   s_last;

    const int t    = threadIdx.x;
    const int c    = blockIdx.x >> 4;        // query combo 0..7
    const int sblk = blockIdx.x & 15;
    const int cc   = c ^ 1;                  // candidate combo (other array)

    for (int i = t; i < NPTS; i += 256) scand[i] = g_sorted[cc][i];
    for (int i = t; i < NBK + 1; i += 256) sbst[i] = g_bstart[cc][i];
    __syncthreads();

    const int wj = t >> 5, ln = t & 31;
    const int q  = (sblk + 16 * wj) * 32 + ln;   // strided query-warp

    const float4 Q = g_sorted[c][q];
    const float qx = Q.x, qy = Q.y, qz = Q.z;
    const float sq = -2.0f * Q.w;                 // |q|^2

    const int b0 = bucket_of(qx);
    float M = -INFF;
    int bl = b0, br = b0;                         // visited = [bl, br)

    while (true) {
        const float dL = (bl > 0)   ? fmaxf(qx - (XLO + bl * XW), 0.0f) : INFF;
        const float dR = (br < NBK) ? fmaxf((XLO + br * XW) - qx, 0.0f) : INFF;
        const float dl2 = dL * dL;
        const float dr2 = dR * dR;
        const float bd  = fmaf(-2.0f, M, sq);     // current best d2 (+inf if M=-inf)
        if (fminf(dl2, dr2) >= bd) break;

        int bsc;
        if (dl2 <= dr2) { bl--; bsc = bl; }
        else            { bsc = br; br++; }

        const int s = sbst[bsc];
        const int e = sbst[bsc + 1];
        for (int i = s; i < e; i++) {
            const float4 C = scand[i];
            const float tt = fmaf(qx, C.x, fmaf(qy, C.y, fmaf(qz, C.z, C.w)));
            M = fmaxf(M, tt);
        }
    }

    float v = fmaf(-2.0f, M, sq);                 // this query's min d2

    // block reduction
#pragma unroll
    for (int o = 16; o; o >>= 1) v += __shfl_down_sync(0xffffffffu, v, o);
    if (ln == 0) s_red[wj] = v;
    __syncthreads();

    if (t == 0) {
        float r = 0.0f;
#pragma unroll
        for (int g = 0; g < 8; g++) r += s_red[g];
        g_partial[blockIdx.x] = r;
        __threadfence();
        const int old = atomicAdd(&g_count, 1);
        s_last = (old == SBLK - 1);
    }
    __syncthreads();

    // last block: warp 0 sums the 128 partials in fixed order (deterministic)
    if (s_last && wj == 0) {
        __threadfence();
        float s = 0.0f;
#pragma unroll
        for (int k = 0; k < SBLK / 32; k++) s += g_partial[ln + k * 32];
#pragma unroll
        for (int o = 16; o; o >>= 1) s += __shfl_down_sync(0xffffffffu, s, o);
        if (ln == 0) {
            out[0] = s * (100.0f / 32768.0f);
            g_count = 0;      // reset for next graph replay
        }
    }
}

extern "C" void kernel_launch(void* const* d_in, const int* in_sizes, int n_in,
                              void* d_out, int out_size)
{
    const float* a1 = (const float*)d_in[0];
    const float* a2 = (const float*)d_in[1];
    float* out = (float*)d_out;

    cudaFuncSetAttribute(chamfer_search,
                         cudaFuncAttributeMaxDynamicSharedMemorySize,
                         NPTS * sizeof(float4));

    chamfer_prep<<<8, 512>>>(a1, a2);
    chamfer_search<<<SBLK, 256, NPTS * sizeof(float4)>>>(out);
}

// round 8
// speedup vs baseline: 1.4600x; 1.4600x over previous
#include <cuda_runtime.h>
#include <cstdint>

// Chamfer distance via 1-D pruned, WARP-COHERENT NN search.
// array1, array2 [B=4, N=4096, D=3] fp32.
// out = (100/32768) * sum over all 32768 per-point NN sq-dists (both dirs).
//
// min d2 = sq - 2*max(q.c - 0.5|c|^2) over a candidate window that provably
// contains the true NN.
//
// Kernel 1 (prep, unchanged from R7): bucket each of the 8 (batch, array)
// combos by x into 512 linear buckets over [-6,6] (clamped). Result is exact
// and order-independent, so within-bucket scatter nondeterminism is harmless.
//
// Kernel 2 (search): R7 failed because each thread walked its own candidate
// list (serial dependent chain, scattered LDS, divergence, 8 warps/SM).
// R8: a WARP owns 32 consecutive sorted queries and scans ONE shared window:
//   phase A: each lane scans 40 rank-neighbors (never empty) -> bound M_est
//   window:  r = sqrt(max(sq-2M,0)); warp-reduce [min(qx-r), max(qx+r)]
//            -> bucket range -> candidate index range (superset of true NN
//            for every lane => exact, deterministic)
//   phase B: uniform loop over [lo,hi): 1 broadcast LDS.128 + 4 instr/lane
//            = 5 issue slots per 32 query-pairs (R6-grade efficiency).
// Two split-warps per query group scan interleaved candidate parities
// (identical window, computed redundantly from identical smem) -> 2048 warps
// chip-wide (~14/SM) for latency hiding; min-combined via smem.
// Final sum: per-block partial + atomic-counter last-block reduce.

#define NBK 512
#define XLO (-6.0f)
#define XW (12.0f / NBK)
#define XINVW (NBK / 12.0f)
#define NPTS 4096
#define SBLK 256             // search grid blocks
#define QPB 128              // queries per block
#define NEG3 (-3.0e38f)

__device__ float4 g_sorted[8][NPTS];
__device__ int    g_bstart[8][NBK + 1];
__device__ float  g_partial[SBLK];
__device__ int    g_count;   // zero-init; self-resets each run

__device__ __forceinline__ int bucket_of(float x) {
    int bk = (int)((x - XLO) * XINVW);
    bk = bk < 0 ? 0 : bk;
    return bk > NBK - 1 ? NBK - 1 : bk;
}

// ---------------- kernel 1: bucket the 8 arrays by x ----------------
__global__ __launch_bounds__(512) void chamfer_prep(
    const float* __restrict__ a1, const float* __restrict__ a2)
{
    __shared__ int sh[NBK];    // histogram -> inclusive scan
    __shared__ int soff[NBK];  // scatter counters

    const int c = blockIdx.x;            // combo 0..7 = b*2 + arr
    const int b = c >> 1;
    const float* src = ((c & 1) ? a2 : a1) + (size_t)b * NPTS * 3;
    const int t = threadIdx.x;           // 512 == NBK

    sh[t] = 0;
    __syncthreads();

    float px[8], py[8], pz[8];
    int   bk[8];
#pragma unroll
    for (int k = 0; k < 8; k++) {
        const int i = t + k * 512;
        px[k] = src[i * 3 + 0];
        py[k] = src[i * 3 + 1];
        pz[k] = src[i * 3 + 2];
        bk[k] = bucket_of(px[k]);
        atomicAdd(&sh[bk[k]], 1);
    }
    __syncthreads();

    for (int off = 1; off < NBK; off <<= 1) {     // inclusive scan
        const int v = (t >= off) ? sh[t - off] : 0;
        __syncthreads();
        sh[t] += v;
        __syncthreads();
    }

    const int e = (t == 0) ? 0 : sh[t - 1];
    soff[t] = e;
    g_bstart[c][t] = e;
    if (t == 0) g_bstart[c][NBK] = NPTS;
    __syncthreads();

#pragma unroll
    for (int k = 0; k < 8; k++) {
        const int r = atomicAdd(&soff[bk[k]], 1);
        g_sorted[c][r] = make_float4(px[k], py[k], pz[k],
            -0.5f * (px[k] * px[k] + py[k] * py[k] + pz[k] * pz[k]));
    }
}

// ---------------- kernel 2: warp-coherent pruned search ----------------
__global__ __launch_bounds__(256) void chamfer_search(float* __restrict__ out)
{
    extern __shared__ float4 scand[];        // 4096 * 16 B = 64 KB (dynamic)
    __shared__ int   sbst[NBK + 1];
    __shared__ float s_v[2][QPB];
    __shared__ float s_red[8];
    __shared__ int   s_last;

    const int t   = threadIdx.x;
    const int wid = t >> 5, ln = t & 31;
    const int grp = wid >> 1;                // query group 0..3 (32 queries)
    const int sp  = wid & 1;                 // candidate-parity split 0/1
    const int c   = blockIdx.x >> 5;         // query combo 0..7
    const int cc  = c ^ 1;                   // candidate combo

    for (int i = t; i < NPTS; i += 256) scand[i] = g_sorted[cc][i];
    for (int i = t; i < NBK + 1; i += 256) sbst[i] = g_bstart[cc][i];
    __syncthreads();

    const int q = (blockIdx.x & 31) * QPB + grp * 32 + ln;   // sorted query
    const float4 Q = g_sorted[c][q];
    const float qx = Q.x, qy = Q.y, qz = Q.z;
    const float sq = -2.0f * Q.w;            // |q|^2

    // phase A: 40 rank-neighbors (never empty) -> initial bound
    const int idx0 = sbst[bucket_of(qx)];
    const int s0 = max(idx0 - 20, 0);
    const int e0 = min(idx0 + 20, NPTS);
    float M0 = NEG3, M1 = NEG3;
    for (int i = s0; i < e0; i++) {
        const float4 C = scand[i];
        const float tt = fmaf(qx, C.x, fmaf(qy, C.y, fmaf(qz, C.z, C.w)));
        M0 = fmaxf(M0, tt);
    }

    // window: r covers the true NN for this lane; union over the warp
    const float bd0 = fmaxf(fmaf(-2.0f, M0, sq), 0.0f);
    const float r   = sqrtf(bd0);
    float lox = qx - r, hix = qx + r;
#pragma unroll
    for (int o = 16; o; o >>= 1) {
        lox = fminf(lox, __shfl_xor_sync(0xffffffffu, lox, o));
        hix = fmaxf(hix, __shfl_xor_sync(0xffffffffu, hix, o));
    }
    const int lo = sbst[bucket_of(lox)];
    const int hi = sbst[bucket_of(hix) + 1];

    // phase B: uniform warp loop, broadcast LDS.128; this warp takes parity sp
    int i = lo + sp;
    for (; i + 2 < hi; i += 4) {
        const float4 C0 = scand[i];
        const float4 C1 = scand[i + 2];
        const float t0 = fmaf(qx, C0.x, fmaf(qy, C0.y, fmaf(qz, C0.z, C0.w)));
        const float t1 = fmaf(qx, C1.x, fmaf(qy, C1.y, fmaf(qz, C1.z, C1.w)));
        M0 = fmaxf(M0, t0);
        M1 = fmaxf(M1, t1);
    }
    for (; i < hi; i += 2) {
        const float4 C = scand[i];
        const float tt = fmaf(qx, C.x, fmaf(qy, C.y, fmaf(qz, C.z, C.w)));
        M0 = fmaxf(M0, tt);
    }

    s_v[sp][grp * 32 + ln] = fmaf(-2.0f, fmaxf(M0, M1), sq);
    __syncthreads();

    // combine splits (exact min), then block sum
    float v = 0.0f;
    if (t < QPB) v = fminf(s_v[0][t], s_v[1][t]);
#pragma unroll
    for (int o = 16; o; o >>= 1) v += __shfl_down_sync(0xffffffffu, v, o);
    if (ln == 0) s_red[wid] = v;
    __syncthreads();

    if (t == 0) {
        float rsum = 0.0f;
#pragma unroll
        for (int g = 0; g < 8; g++) rsum += s_red[g];
        g_partial[blockIdx.x] = rsum;
        __threadfence();
        const int old = atomicAdd(&g_count, 1);
        s_last = (old == SBLK - 1);
    }
    __syncthreads();

    // last block: warp 0 sums the 256 partials in fixed order (deterministic)
    if (s_last && wid == 0) {
        __threadfence();
        float s = 0.0f;
#pragma unroll
        for (int k = 0; k < SBLK / 32; k++) s += g_partial[ln + k * 32];
#pragma unroll
        for (int o = 16; o; o >>= 1) s += __shfl_down_sync(0xffffffffu, s, o);
        if (ln == 0) {
            out[0] = s * (100.0f / 32768.0f);
            g_count = 0;      // reset for next graph replay
        }
    }
}

extern "C" void kernel_launch(void* const* d_in, const int* in_sizes, int n_in,
                              void* d_out, int out_size)
{
    const float* a1 = (const float*)d_in[0];
    const float* a2 = (const float*)d_in[1];
    float* out = (float*)d_out;

    cudaFuncSetAttribute(chamfer_search,
                         cudaFuncAttributeMaxDynamicSharedMemorySize,
                         NPTS * sizeof(float4));

    chamfer_prep<<<8, 512>>>(a1, a2);
    chamfer_search<<<SBLK, 256, NPTS * sizeof(float4)>>>(out);
}